// round 1
// baseline (speedup 1.0000x reference)
#include <cuda_runtime.h>
#include <math.h>

// Problem dims (fixed by reference)
#define IN_DIM 1024
#define H_DIM  1024
#define C_DIM  16
#define B_DIM  4096
#define N_DIM  (C_DIM * 2 * H_DIM)        // 32768
#define K_HALF 1024                        // per-phase K (IN or H)

#define BM 128
#define BN 128
#define BK 8
#define TM 8
#define TN 8

static const size_t HALF_OUT = (size_t)B_DIM * C_DIM * H_DIM;  // cell_input count

__global__ __launch_bounds__(256)
void gate_gemm_kernel(const float* __restrict__ input_word,  // [B, IN]
                      const float* __restrict__ hidden,      // [B, H]
                      const float* __restrict__ Wx,          // [C, 2H, IN] = [N, IN]
                      const float* __restrict__ bx,          // [C, 2H] = [N]
                      const float* __restrict__ Wh,          // [C, 2H, H] = [N, H]
                      float* __restrict__ out)               // [cell_input | input_gate]
{
    __shared__ float As[BK][BM];
    __shared__ float Bs[BK][BN];

    const int tid = threadIdx.x;
    const int bm = blockIdx.y * BM;   // batch tile start
    const int bn = blockIdx.x * BN;   // output-feature tile start (n = c*2048 + o)

    // 16x16 thread grid, each thread owns an 8x8 micro-tile
    const int row_t = tid >> 4;       // 0..15
    const int col_t = tid & 15;       // 0..15

    // tile-load mapping: each thread loads one float4 of A and one of B
    const int ld_row = tid >> 1;          // 0..127
    const int ld_k4  = (tid & 1) * 4;     // 0 or 4

    float acc[TM][TN];
    #pragma unroll
    for (int i = 0; i < TM; i++)
        #pragma unroll
        for (int j = 0; j < TN; j++)
            acc[i][j] = 0.f;

    #pragma unroll 1
    for (int phase = 0; phase < 2; ++phase) {
        const float* Ag = phase ? hidden : input_word;   // [rows, 1024] K-major
        const float* Bg = phase ? Wh : Wx;               // [N, 1024]   K-major

        const float* a_ptr = Ag + (size_t)(bm + ld_row) * K_HALF + ld_k4;
        const float* b_ptr = Bg + (size_t)(bn + ld_row) * K_HALF + ld_k4;

        #pragma unroll 1
        for (int k0 = 0; k0 < K_HALF; k0 += BK) {
            float4 av = *(const float4*)(a_ptr + k0);
            float4 bv = *(const float4*)(b_ptr + k0);

            __syncthreads();   // previous tile fully consumed
            As[ld_k4 + 0][ld_row] = av.x;
            As[ld_k4 + 1][ld_row] = av.y;
            As[ld_k4 + 2][ld_row] = av.z;
            As[ld_k4 + 3][ld_row] = av.w;
            Bs[ld_k4 + 0][ld_row] = bv.x;
            Bs[ld_k4 + 1][ld_row] = bv.y;
            Bs[ld_k4 + 2][ld_row] = bv.z;
            Bs[ld_k4 + 3][ld_row] = bv.w;
            __syncthreads();   // tile ready

            #pragma unroll
            for (int kk = 0; kk < BK; ++kk) {
                float a_frag[TM], b_frag[TN];
                #pragma unroll
                for (int i = 0; i < TM; i++) a_frag[i] = As[kk][row_t * TM + i];
                #pragma unroll
                for (int j = 0; j < TN; j++) b_frag[j] = Bs[kk][col_t * TN + j];
                #pragma unroll
                for (int i = 0; i < TM; i++)
                    #pragma unroll
                    for (int j = 0; j < TN; j++)
                        acc[i][j] = fmaf(a_frag[i], b_frag[j], acc[i][j]);
            }
        }
    }

    // ---- epilogue: bias + activation + scatter ----
    // A whole BN=128 tile lies in one c and one gate/cell half (halves are 1024-aligned).
    const int  c        = bn >> 11;                   // n / 2048
    const int  o_tile   = bn & 2047;                  // o of tile start
    const bool is_gate  = (o_tile < H_DIM);           // o < 1024 -> input_gate (sigmoid)
    const int  o_base   = (o_tile & 1023) + col_t * TN;  // offset within the 1024-wide half

    float* obase = is_gate ? (out + HALF_OUT) : out;

    float bias[TN];
    #pragma unroll
    for (int j = 0; j < TN; j++)
        bias[j] = __ldg(bx + bn + col_t * TN + j);

    #pragma unroll
    for (int i = 0; i < TM; i++) {
        const int gm = bm + row_t * TM + i;
        float v[TN];
        #pragma unroll
        for (int j = 0; j < TN; j++) {
            float x = acc[i][j] + bias[j];
            if (is_gate) {
                // sigmoid
                v[j] = 1.f / (1.f + __expf(-x));
            } else {
                // tanh via exp: tanh(x) = 2*sigmoid(2x) - 1
                v[j] = 2.f / (1.f + __expf(-2.f * x)) - 1.f;
            }
        }
        float* op = obase + ((size_t)gm * C_DIM + c) * H_DIM + o_base;
        *(float4*)(op + 0) = make_float4(v[0], v[1], v[2], v[3]);
        *(float4*)(op + 4) = make_float4(v[4], v[5], v[6], v[7]);
    }
}

extern "C" void kernel_launch(void* const* d_in, const int* in_sizes, int n_in,
                              void* d_out, int out_size) {
    const float* input_word = (const float*)d_in[0];  // [4096, 1024]
    const float* hidden     = (const float*)d_in[1];  // [4096, 1024]
    const float* Wx         = (const float*)d_in[2];  // [16, 2048, 1024]
    const float* bx         = (const float*)d_in[3];  // [16, 2048]
    const float* Wh         = (const float*)d_in[4];  // [16, 2048, 1024]
    float* out              = (float*)d_out;

    dim3 grid(N_DIM / BN, B_DIM / BM);   // (256, 32)
    dim3 block(256);
    gate_gemm_kernel<<<grid, block>>>(input_word, hidden, Wx, bx, Wh, out);
}

// round 4
// speedup vs baseline: 3.0852x; 3.0852x over previous
#include <cuda_runtime.h>
#include <cstdint>
#include <math.h>

// ---------------- problem dims ----------------
#define C_DIM  16
#define B_DIM  4096
#define N_DIM  32768           // C * 2H
#define K_HALF 1024

// ---------------- tiling ----------------
#define BM 128
#define BN 128
#define BK 32                  // floats per k-slab
#define NSTAGE 3
#define NITER 64               // 2048 / 32

#define A_TILE_BYTES (BM * BK * 4)     // 16384
#define B_TILE_BYTES (BN * BK * 4)     // 16384
#define STAGE_BYTES  (A_TILE_BYTES + B_TILE_BYTES)   // 32768
#define SMEM_TOTAL   (NSTAGE * STAGE_BYTES)          // 98304

static const size_t HALF_OUT = (size_t)B_DIM * C_DIM * 1024;

__device__ __forceinline__ uint32_t smem_u32(const void* p) {
    uint32_t a;
    asm("{ .reg .u64 t; cvta.to.shared.u64 t, %1; cvt.u32.u64 %0, t; }" : "=r"(a) : "l"(p));
    return a;
}

#define CP_ASYNC16(dst, src) \
    asm volatile("cp.async.cg.shared.global [%0], [%1], 16;" :: "r"(dst), "l"(src))
#define CP_COMMIT() asm volatile("cp.async.commit_group;")
#define CP_WAIT1()  asm volatile("cp.async.wait_group 1;")

#define LDSM_X4(r0, r1, r2, r3, a) \
    asm volatile("ldmatrix.sync.aligned.m8n8.x4.shared.b16 {%0,%1,%2,%3}, [%4];" \
                 : "=r"(r0), "=r"(r1), "=r"(r2), "=r"(r3) : "r"(a))

__device__ __forceinline__ uint32_t to_tf32(uint32_t x) {
    uint32_t y;
    asm("cvt.rna.tf32.f32 %0, %1;" : "=r"(y) : "f"(__uint_as_float(x)));
    return y;
}

#define MMA_TF32(c, a, b0, b1)                                                   \
    asm volatile("mma.sync.aligned.m16n8k8.row.col.f32.tf32.tf32.f32 "           \
                 "{%0,%1,%2,%3}, {%4,%5,%6,%7}, {%8,%9}, {%0,%1,%2,%3};"         \
                 : "+f"((c)[0]), "+f"((c)[1]), "+f"((c)[2]), "+f"((c)[3])        \
                 : "r"((a)[0]), "r"((a)[1]), "r"((a)[2]), "r"((a)[3]),           \
                   "r"(b0), "r"(b1))

__global__ void __launch_bounds__(256, 1)
gate_mma_kernel(const float* __restrict__ Xw,   // [4096, 1024]
                const float* __restrict__ Hd,   // [4096, 1024]
                const float* __restrict__ Wx,   // [32768, 1024]
                const float* __restrict__ bx,   // [32768]
                const float* __restrict__ Wh,   // [32768, 1024]
                float* __restrict__ out)
{
    extern __shared__ char smem[];
    const uint32_t sb = smem_u32(smem);

    const int tid  = threadIdx.x;
    const int lane = tid & 31;
    const int warp = tid >> 5;
    const int wm   = warp >> 2;          // 0..1
    const int wn   = warp & 3;           // 0..3

    const int bm = blockIdx.x * BM;      // M fastest: A tiles L2-resident
    const int bn = blockIdx.y * BN;

    // ---- cp.async mapping: thread -> (row, 4 chunks of 16B) ----
    const int lm = tid >> 1;             // 0..127 (tile row)
    const int lk = (tid & 1) * 4;        // chunk base 0 or 4 (of 8 per row)

    // ---- ldmatrix per-lane address pieces ----
    const int l7 = lane & 7;
    const int am_off = l7 + ((lane >> 3) & 1) * 8;   // A: q1,q3 -> +8 rows
    const int aq     = (lane >> 4) & 1;              // A: q2,q3 -> kc+1
    const int bn_off = l7 + ((lane >> 4) & 1) * 8;   // B: q2,q3 -> +8 rows
    const int bq     = (lane >> 3) & 1;              // B: q1,q3 -> kc+1

    float acc[4][4][4];
    #pragma unroll
    for (int i = 0; i < 4; i++)
        #pragma unroll
        for (int j = 0; j < 4; j++)
            #pragma unroll
            for (int k = 0; k < 4; k++)
                acc[i][j][k] = 0.f;

    // ---- stage loader ----
    auto load_stage = [&](int s, int it) {
        const float* Ab = (it < 32) ? Xw : Hd;
        const float* Bb = (it < 32) ? Wx : Wh;
        const int k0 = (it & 31) * BK;
        const float* asrc = Ab + (size_t)(bm + lm) * K_HALF + k0;
        const float* bsrc = Bb + (size_t)(bn + lm) * K_HALF + k0;
        const uint32_t arow = sb + s * STAGE_BYTES + lm * 128;
        const uint32_t brow = sb + s * STAGE_BYTES + A_TILE_BYTES + lm * 128;
        #pragma unroll
        for (int j = 0; j < 4; j++) {
            const int kc = lk + j;
            const int sw = (kc ^ (lm & 7)) << 4;
            CP_ASYNC16(arow + sw, asrc + kc * 4);
            CP_ASYNC16(brow + sw, bsrc + kc * 4);
        }
    };

    // ---- prologue ----
    load_stage(0, 0); CP_COMMIT();
    load_stage(1, 1); CP_COMMIT();

    // ---- mainloop ----
    #pragma unroll 1
    for (int it = 0; it < NITER; it++) {
        CP_WAIT1();
        __syncthreads();

        if (it + 2 < NITER) load_stage((it + 2) % NSTAGE, it + 2);
        CP_COMMIT();   // empty groups keep wait_group(1) semantics exact

        const int s = it % NSTAGE;
        const uint32_t a_base = sb + s * STAGE_BYTES;
        const uint32_t b_base = a_base + A_TILE_BYTES;

        #pragma unroll
        for (int ks = 0; ks < 4; ks++) {
            uint32_t ar[4][4], br[2][4];
            #pragma unroll
            for (int mf = 0; mf < 4; mf++) {
                const int m = wm * 64 + mf * 16 + am_off;
                const uint32_t addr = a_base + m * 128 + (((2 * ks + aq) ^ l7) << 4);
                LDSM_X4(ar[mf][0], ar[mf][1], ar[mf][2], ar[mf][3], addr);
            }
            #pragma unroll
            for (int j = 0; j < 2; j++) {
                const int n = wn * 32 + j * 16 + bn_off;
                const uint32_t addr = b_base + n * 128 + (((2 * ks + bq) ^ l7) << 4);
                LDSM_X4(br[j][0], br[j][1], br[j][2], br[j][3], addr);
            }
            #pragma unroll
            for (int mf = 0; mf < 4; mf++)
                #pragma unroll
                for (int r = 0; r < 4; r++)
                    ar[mf][r] = to_tf32(ar[mf][r]);
            #pragma unroll
            for (int j = 0; j < 2; j++)
                #pragma unroll
                for (int r = 0; r < 4; r++)
                    br[j][r] = to_tf32(br[j][r]);

            #pragma unroll
            for (int mf = 0; mf < 4; mf++) {
                #pragma unroll
                for (int nf = 0; nf < 4; nf++) {
                    const int j = nf >> 1, h = (nf & 1) * 2;
                    MMA_TF32(acc[mf][nf], ar[mf], br[j][h], br[j][h + 1]);
                }
            }
        }
        __syncthreads();
    }

    // ---- epilogue: bias + activation + scatter ----
    const int  c_blk   = bn >> 11;
    const bool is_gate = (bn & 2047) < 1024;        // sigmoid half -> input_gate
    const int  o_tile  = bn & 1023;
    float* obase = is_gate ? (out + HALF_OUT) : out;

    #pragma unroll
    for (int mf = 0; mf < 4; mf++) {
        const int m0 = bm + wm * 64 + mf * 16 + (lane >> 2);
        #pragma unroll
        for (int nf = 0; nf < 4; nf++) {
            const int n_loc = wn * 32 + nf * 8 + (lane & 3) * 2;
            const float b0 = __ldg(bx + bn + n_loc);
            const float b1 = __ldg(bx + bn + n_loc + 1);
            const int o = o_tile + n_loc;
            #pragma unroll
            for (int h = 0; h < 2; h++) {            // rows m0, m0+8
                const int m = m0 + h * 8;
                float x0 = acc[mf][nf][h * 2 + 0] + b0;
                float x1 = acc[mf][nf][h * 2 + 1] + b1;
                float2 v;
                if (is_gate) {
                    v.x = 1.f / (1.f + __expf(-x0));
                    v.y = 1.f / (1.f + __expf(-x1));
                } else {
                    v.x = 2.f / (1.f + __expf(-2.f * x0)) - 1.f;
                    v.y = 2.f / (1.f + __expf(-2.f * x1)) - 1.f;
                }
                *(float2*)(obase + ((size_t)m * C_DIM + c_blk) * 1024 + o) = v;
            }
        }
    }
}

extern "C" void kernel_launch(void* const* d_in, const int* in_sizes, int n_in,
                              void* d_out, int out_size) {
    const float* input_word = (const float*)d_in[0];
    const float* hidden     = (const float*)d_in[1];
    const float* Wx         = (const float*)d_in[2];
    const float* bx         = (const float*)d_in[3];
    const float* Wh         = (const float*)d_in[4];

    static bool attr_set = false;
    if (!attr_set) {
        cudaFuncSetAttribute(gate_mma_kernel,
                             cudaFuncAttributeMaxDynamicSharedMemorySize, SMEM_TOTAL);
        attr_set = true;
    }

    dim3 grid(B_DIM / BM, N_DIM / BN);   // (32, 256), M fastest
    gate_mma_kernel<<<grid, 256, SMEM_TOTAL>>>(input_word, hidden, Wx, bx, Wh,
                                               (float*)d_out);
}